// round 1
// baseline (speedup 1.0000x reference)
#include <cuda_runtime.h>
#include <cuda_bf16.h>

// ---------------- problem constants ----------------
#define E_      8
#define DIN     2048
#define DOUT    2048
#define RANK    8
#define ER      64          // E * RANK
#define M_      8192        // 2 * 4096 tokens
#define HR      72          // E + ER (router logits + all low-rank dots)
#define MAIN_OUT (M_*DOUT)  // 16,777,216
#define W_OUT    (M_*E_)    // 65,536
// SCALING = ALPHA/RANK = 1.0

// ---------------- scratch (device globals: no allocations allowed) ----------------
__device__ float g_hraw[(size_t)M_ * HR];   // [token][72]: 8 logits then 64 h values
__device__ float g_hp[(size_t)M_ * ER];     // weighted low-rank activations
__device__ float g_BsT[(size_t)DOUT * ER];  // BsT[o][k] = Bm[k/8][o][k%8]

// =====================================================================
// Kernel A: hraw = x @ concat(Wr, A)^T      (GEMM 8192 x 72, K = 2048)
//   block: 256 threads, 32 tokens; token = tid/8, jgroup = tid%8 (9 outputs)
//   SMEM: xs[32][132] + as[72][132]  (132-float stride -> conflict-free f4)
// =====================================================================
#define A_TOKENS 32
#define A_CHUNK  128
#define A_STR    132

__global__ __launch_bounds__(256)
void k_hraw(const float* __restrict__ x,
            const float* __restrict__ Wr,
            const float* __restrict__ A)
{
    extern __shared__ float sh[];
    float* xs  = sh;                         // [A_TOKENS][A_STR]
    float* as_ = sh + A_TOKENS * A_STR;      // [HR][A_STR]

    const int tid = threadIdx.x;
    const int t0  = blockIdx.x * A_TOKENS;
    const int tok = tid >> 3;                // 0..31
    const int jg  = tid & 7;                 // 0..7

    float acc[9];
#pragma unroll
    for (int j = 0; j < 9; j++) acc[j] = 0.f;

    for (int dc = 0; dc < DIN; dc += A_CHUNK) {
        // stage x chunk: 32 x 128 floats (4 float4 per thread)
        {
            const int r  = tid >> 3;         // row 0..31
            const int c4 = tid & 7;          // 0..7
            const float* src = x + (size_t)(t0 + r) * DIN + dc;
#pragma unroll
            for (int i = 0; i < 4; i++) {
                float4 v = *(const float4*)(src + (c4 + i * 8) * 4);
                *(float4*)(xs + r * A_STR + (c4 + i * 8) * 4) = v;
            }
        }
        // stage Acat chunk: 72 x 128 floats (9 float4 per thread)
#pragma unroll
        for (int i = 0; i < 9; i++) {
            const int l  = tid + i * 256;    // 0..2303
            const int r  = l >> 5;           // row 0..71
            const int c4 = l & 31;
            const float* src = (r < E_) ? (Wr + (size_t)r * DIN)
                                        : (A  + (size_t)(r - E_) * DIN);
            float4 v = *(const float4*)(src + dc + c4 * 4);
            *(float4*)(as_ + r * A_STR + c4 * 4) = v;
        }
        __syncthreads();

        const float* xrow = xs + tok * A_STR;
#pragma unroll 2
        for (int d4 = 0; d4 < A_CHUNK / 4; d4++) {
            const float4 xv = *(const float4*)(xrow + d4 * 4);
#pragma unroll
            for (int j = 0; j < 9; j++) {
                const float4 av = *(const float4*)(as_ + (jg * 9 + j) * A_STR + d4 * 4);
                acc[j] = fmaf(av.x, xv.x, acc[j]);
                acc[j] = fmaf(av.y, xv.y, acc[j]);
                acc[j] = fmaf(av.z, xv.z, acc[j]);
                acc[j] = fmaf(av.w, xv.w, acc[j]);
            }
        }
        __syncthreads();
    }

    const int gt = t0 + tok;
#pragma unroll
    for (int j = 0; j < 9; j++)
        g_hraw[(size_t)gt * HR + jg * 9 + j] = acc[j];
}

// =====================================================================
// Kernel A2: per-token softmax over 8 logits, fold weights into hp,
//            write router weights to the tail of d_out.
// =====================================================================
__global__ void k_softmax(const float* __restrict__ br,
                          float* __restrict__ wout, int write_w)
{
    const int t = blockIdx.x * blockDim.x + threadIdx.x;
    if (t >= M_) return;
    const float* row = g_hraw + (size_t)t * HR;

    float l[E_];
    float mx = -1e30f;
#pragma unroll
    for (int e = 0; e < E_; e++) { l[e] = row[e] + br[e]; mx = fmaxf(mx, l[e]); }
    float s = 0.f;
#pragma unroll
    for (int e = 0; e < E_; e++) { l[e] = expf(l[e] - mx); s += l[e]; }
    const float inv = 1.f / s;
#pragma unroll
    for (int e = 0; e < E_; e++) l[e] *= inv;

    if (write_w) {
#pragma unroll
        for (int e = 0; e < E_; e++) wout[(size_t)t * E_ + e] = l[e];
    }
#pragma unroll
    for (int k = 0; k < ER; k++)
        g_hp[(size_t)t * ER + k] = l[k >> 3] * row[E_ + k];   // SCALING = 1
}

// =====================================================================
// Kernel A3: BsT[o][k] = Bm[k/8][o][k%8]
// =====================================================================
__global__ void k_bsmall(const float* __restrict__ Bm)
{
    const int idx = blockIdx.x * blockDim.x + threadIdx.x;
    if (idx >= DOUT * ER) return;
    const int o = idx >> 6;
    const int k = idx & 63;
    g_BsT[(size_t)o * ER + k] =
        Bm[(size_t)(k >> 3) * DOUT * RANK + (size_t)o * RANK + (k & 7)];
}

// =====================================================================
// Kernel B: out = x @ Wf^T + bf + hp @ BsT
//   128x128 tile, BK=16, 256 threads, 8x8 microtile, double-buffered SMEM.
//   K-tiles 0..127 read x/Wf; K-tiles 128..131 read hp/BsT.
// =====================================================================
#define KT_MAIN 128
#define KT_ALL  132

__global__ __launch_bounds__(256)
void k_gemm(const float* __restrict__ x,
            const float* __restrict__ Wf,
            const float* __restrict__ bf,
            float* __restrict__ out)
{
    __shared__ float As[2][16][128];
    __shared__ float Bs[2][16][128];

    const int tid  = threadIdx.x;
    const int m0   = blockIdx.y * 128;
    const int n0   = blockIdx.x * 128;
    const int lrow = tid >> 2;          // 0..63
    const int lcol = (tid & 3) * 4;     // 0,4,8,12
    const int ty   = tid >> 4;          // 0..15
    const int tx   = tid & 15;          // 0..15

    float acc[8][8];
#pragma unroll
    for (int i = 0; i < 8; i++)
#pragma unroll
        for (int j = 0; j < 8; j++) acc[i][j] = 0.f;

    float4 a0, a1, b0, b1;

#define FETCH(kt) do {                                                        \
    if ((kt) < KT_MAIN) {                                                     \
        const float* ap = x  + (size_t)(m0 + lrow) * DIN + (kt) * 16 + lcol;  \
        const float* bp = Wf + (size_t)(n0 + lrow) * DIN + (kt) * 16 + lcol;  \
        a0 = *(const float4*)ap;  a1 = *(const float4*)(ap + (size_t)64 * DIN); \
        b0 = *(const float4*)bp;  b1 = *(const float4*)(bp + (size_t)64 * DIN); \
    } else {                                                                  \
        const int kk = ((kt) - KT_MAIN) * 16 + lcol;                          \
        const float* ap = g_hp  + (size_t)(m0 + lrow) * ER + kk;              \
        const float* bp = g_BsT + (size_t)(n0 + lrow) * ER + kk;              \
        a0 = *(const float4*)ap;  a1 = *(const float4*)(ap + 64 * ER);        \
        b0 = *(const float4*)bp;  b1 = *(const float4*)(bp + 64 * ER);        \
    } } while (0)

#define STORE(buf) do {                                                       \
    As[buf][lcol + 0][lrow]      = a0.x; As[buf][lcol + 1][lrow]      = a0.y; \
    As[buf][lcol + 2][lrow]      = a0.z; As[buf][lcol + 3][lrow]      = a0.w; \
    As[buf][lcol + 0][lrow + 64] = a1.x; As[buf][lcol + 1][lrow + 64] = a1.y; \
    As[buf][lcol + 2][lrow + 64] = a1.z; As[buf][lcol + 3][lrow + 64] = a1.w; \
    Bs[buf][lcol + 0][lrow]      = b0.x; Bs[buf][lcol + 1][lrow]      = b0.y; \
    Bs[buf][lcol + 2][lrow]      = b0.z; Bs[buf][lcol + 3][lrow]      = b0.w; \
    Bs[buf][lcol + 0][lrow + 64] = b1.x; Bs[buf][lcol + 1][lrow + 64] = b1.y; \
    Bs[buf][lcol + 2][lrow + 64] = b1.z; Bs[buf][lcol + 3][lrow + 64] = b1.w; \
    } while (0)

    FETCH(0);
    STORE(0);
    __syncthreads();

    int cur = 0;
    for (int kt = 0; kt < KT_ALL; kt++) {
        const bool has_next = (kt + 1 < KT_ALL);
        if (has_next) FETCH(kt + 1);

#pragma unroll
        for (int k = 0; k < 16; k++) {
            const float4 af0 = *(const float4*)&As[cur][k][ty * 8];
            const float4 af1 = *(const float4*)&As[cur][k][ty * 8 + 4];
            const float4 bf0 = *(const float4*)&Bs[cur][k][tx * 8];
            const float4 bf1 = *(const float4*)&Bs[cur][k][tx * 8 + 4];
            const float av[8] = {af0.x, af0.y, af0.z, af0.w, af1.x, af1.y, af1.z, af1.w};
            const float bv[8] = {bf0.x, bf0.y, bf0.z, bf0.w, bf1.x, bf1.y, bf1.z, bf1.w};
#pragma unroll
            for (int i = 0; i < 8; i++)
#pragma unroll
                for (int j = 0; j < 8; j++)
                    acc[i][j] = fmaf(av[i], bv[j], acc[i][j]);
        }

        if (has_next) {
            STORE(cur ^ 1);
            __syncthreads();
            cur ^= 1;
        }
    }

    // epilogue: + bf, store
    const float4 bv0 = *(const float4*)(bf + n0 + tx * 8);
    const float4 bv1 = *(const float4*)(bf + n0 + tx * 8 + 4);
#pragma unroll
    for (int i = 0; i < 8; i++) {
        float* orow = out + (size_t)(m0 + ty * 8 + i) * DOUT + n0 + tx * 8;
        float4 r0, r1;
        r0.x = acc[i][0] + bv0.x; r0.y = acc[i][1] + bv0.y;
        r0.z = acc[i][2] + bv0.z; r0.w = acc[i][3] + bv0.w;
        r1.x = acc[i][4] + bv1.x; r1.y = acc[i][5] + bv1.y;
        r1.z = acc[i][6] + bv1.z; r1.w = acc[i][7] + bv1.w;
        *(float4*)orow       = r0;
        *(float4*)(orow + 4) = r1;
    }
#undef FETCH
#undef STORE
}

// =====================================================================
// launch
// =====================================================================
extern "C" void kernel_launch(void* const* d_in, const int* in_sizes, int n_in,
                              void* d_out, int out_size)
{
    const float* x  = (const float*)d_in[0];
    const float* Wf = (const float*)d_in[1];
    const float* bf = (const float*)d_in[2];
    const float* Wr = (const float*)d_in[3];
    const float* br = (const float*)d_in[4];
    const float* A  = (const float*)d_in[5];
    const float* Bm = (const float*)d_in[6];
    float* out = (float*)d_out;

    const int write_w = (out_size >= MAIN_OUT + W_OUT) ? 1 : 0;

    const int shbytes = (A_TOKENS + HR) * A_STR * (int)sizeof(float); // 54,912 B
    cudaFuncSetAttribute(k_hraw, cudaFuncAttributeMaxDynamicSharedMemorySize, shbytes);

    k_hraw<<<M_ / A_TOKENS, 256, shbytes>>>(x, Wr, A);
    k_bsmall<<<(DOUT * ER + 255) / 256, 256>>>(Bm);
    k_softmax<<<(M_ + 255) / 256, 256>>>(br, out + MAIN_OUT, write_w);
    k_gemm<<<dim3(DOUT / 128, M_ / 128), 256>>>(x, Wf, bf, out);
}

// round 3
// speedup vs baseline: 2.3155x; 2.3155x over previous
#include <cuda_runtime.h>
#include <cuda_bf16.h>
#include <cstdint>

// ---------------- problem constants ----------------
#define E_      8
#define DIN     2048
#define DOUT    2048
#define RANK    8
#define ER      64
#define M_      8192
#define HR      72
#define MAIN_OUT (M_*DOUT)
#define W_OUT    (M_*E_)

// ---------------- scratch (device globals) ----------------
__device__ __align__(16) float g_hraw[(size_t)M_ * HR];
__device__ __align__(16) __nv_bfloat16 g_xh[(size_t)M_ * DIN];
__device__ __align__(16) __nv_bfloat16 g_xl[(size_t)M_ * DIN];
__device__ __align__(16) __nv_bfloat16 g_Wh[(size_t)DOUT * DIN];
__device__ __align__(16) __nv_bfloat16 g_Wl[(size_t)DOUT * DIN];
__device__ __align__(16) __nv_bfloat16 g_hph[(size_t)M_ * ER];
__device__ __align__(16) __nv_bfloat16 g_hpl[(size_t)M_ * ER];
__device__ __align__(16) __nv_bfloat16 g_Bsh[(size_t)DOUT * ER];
__device__ __align__(16) __nv_bfloat16 g_Bsl[(size_t)DOUT * ER];

// ---------------- PTX helpers (baseline sm_80-class only) ----------------
__device__ __forceinline__ uint32_t smem_u32(const void* p) {
    uint32_t a;
    asm("{ .reg .u64 t; cvta.to.shared.u64 t, %1; cvt.u32.u64 %0, t; }" : "=r"(a) : "l"(p));
    return a;
}
#define CP16(saddr, gptr) \
    asm volatile("cp.async.cg.shared.global [%0], [%1], 16;" :: "r"(saddr), "l"(gptr))
#define CP_COMMIT() asm volatile("cp.async.commit_group;" ::: "memory")
#define CP_WAIT(n)  asm volatile("cp.async.wait_group %0;" :: "n"(n) : "memory")

#define LDSM4(r, a) \
    asm volatile("ldmatrix.sync.aligned.m8n8.x4.shared.b16 {%0,%1,%2,%3}, [%4];" \
        : "=r"((r)[0]), "=r"((r)[1]), "=r"((r)[2]), "=r"((r)[3]) : "r"(a))

#define MMA16816(d, a, b) \
    asm volatile("mma.sync.aligned.m16n8k16.row.col.f32.bf16.bf16.f32 " \
        "{%0,%1,%2,%3}, {%4,%5,%6,%7}, {%8,%9}, {%0,%1,%2,%3};" \
        : "+f"((d)[0]), "+f"((d)[1]), "+f"((d)[2]), "+f"((d)[3]) \
        : "r"((a)[0]), "r"((a)[1]), "r"((a)[2]), "r"((a)[3]), \
          "r"((b)[0]), "r"((b)[1]))

// =====================================================================
// Kernel: split fp32 -> bf16 hi/lo
// =====================================================================
__global__ void k_split(const float* __restrict__ s,
                        __nv_bfloat16* __restrict__ h,
                        __nv_bfloat16* __restrict__ l, int n4)
{
    const int i = blockIdx.x * blockDim.x + threadIdx.x;
    if (i >= n4) return;
    const float4 v = ((const float4*)s)[i];
    float vv[4] = {v.x, v.y, v.z, v.w};
    __nv_bfloat162 hp[2], lp[2];
#pragma unroll
    for (int j = 0; j < 2; j++) {
        __nv_bfloat16 h0 = __float2bfloat16(vv[2*j]);
        __nv_bfloat16 h1 = __float2bfloat16(vv[2*j+1]);
        hp[j] = __nv_bfloat162(h0, h1);
        lp[j] = __nv_bfloat162(__float2bfloat16(vv[2*j]   - __bfloat162float(h0)),
                               __float2bfloat16(vv[2*j+1] - __bfloat162float(h1)));
    }
    ((__nv_bfloat162*)h)[2*i]   = hp[0];
    ((__nv_bfloat162*)h)[2*i+1] = hp[1];
    ((__nv_bfloat162*)l)[2*i]   = lp[0];
    ((__nv_bfloat162*)l)[2*i+1] = lp[1];
}

// =====================================================================
// Kernel A: hraw = x @ concat(Wr, A)^T  (fp32 SIMT)
// =====================================================================
#define A_TOKENS 32
#define A_CHUNK  128
#define A_STR    132

__global__ __launch_bounds__(256)
void k_hraw(const float* __restrict__ x,
            const float* __restrict__ Wr,
            const float* __restrict__ A)
{
    extern __shared__ float sh[];
    float* xs  = sh;
    float* as_ = sh + A_TOKENS * A_STR;

    const int tid = threadIdx.x;
    const int t0  = blockIdx.x * A_TOKENS;
    const int tok = tid >> 3;
    const int jg  = tid & 7;

    float acc[9];
#pragma unroll
    for (int j = 0; j < 9; j++) acc[j] = 0.f;

    for (int dc = 0; dc < DIN; dc += A_CHUNK) {
        {
            const int r  = tid >> 3;
            const int c4 = tid & 7;
            const float* src = x + (size_t)(t0 + r) * DIN + dc;
#pragma unroll
            for (int i = 0; i < 4; i++) {
                float4 v = *(const float4*)(src + (c4 + i * 8) * 4);
                *(float4*)(xs + r * A_STR + (c4 + i * 8) * 4) = v;
            }
        }
#pragma unroll
        for (int i = 0; i < 9; i++) {
            const int l  = tid + i * 256;
            const int r  = l >> 5;
            const int c4 = l & 31;
            const float* src = (r < E_) ? (Wr + (size_t)r * DIN)
                                        : (A  + (size_t)(r - E_) * DIN);
            float4 v = *(const float4*)(src + dc + c4 * 4);
            *(float4*)(as_ + r * A_STR + c4 * 4) = v;
        }
        __syncthreads();

        const float* xrow = xs + tok * A_STR;
#pragma unroll 2
        for (int d4 = 0; d4 < A_CHUNK / 4; d4++) {
            const float4 xv = *(const float4*)(xrow + d4 * 4);
#pragma unroll
            for (int j = 0; j < 9; j++) {
                const float4 av = *(const float4*)(as_ + (jg * 9 + j) * A_STR + d4 * 4);
                acc[j] = fmaf(av.x, xv.x, acc[j]);
                acc[j] = fmaf(av.y, xv.y, acc[j]);
                acc[j] = fmaf(av.z, xv.z, acc[j]);
                acc[j] = fmaf(av.w, xv.w, acc[j]);
            }
        }
        __syncthreads();
    }

    const int gt = t0 + tok;
#pragma unroll
    for (int j = 0; j < 9; j++)
        g_hraw[(size_t)gt * HR + jg * 9 + j] = acc[j];
}

// =====================================================================
// Kernel A2: softmax + fold weights -> hp hi/lo bf16, write w
// =====================================================================
__global__ void k_softmax(const float* __restrict__ br,
                          float* __restrict__ wout, int write_w)
{
    const int t = blockIdx.x * blockDim.x + threadIdx.x;
    if (t >= M_) return;
    const float* row = g_hraw + (size_t)t * HR;

    float l[E_];
    float mx = -1e30f;
#pragma unroll
    for (int e = 0; e < E_; e++) { l[e] = row[e] + br[e]; mx = fmaxf(mx, l[e]); }
    float s = 0.f;
#pragma unroll
    for (int e = 0; e < E_; e++) { l[e] = expf(l[e] - mx); s += l[e]; }
    const float inv = 1.f / s;
#pragma unroll
    for (int e = 0; e < E_; e++) l[e] *= inv;

    if (write_w) {
#pragma unroll
        for (int e = 0; e < E_; e++) wout[(size_t)t * E_ + e] = l[e];
    }
#pragma unroll
    for (int k = 0; k < ER; k++) {
        const float v = l[k >> 3] * row[E_ + k];
        const __nv_bfloat16 h = __float2bfloat16(v);
        g_hph[(size_t)t * ER + k] = h;
        g_hpl[(size_t)t * ER + k] = __float2bfloat16(v - __bfloat162float(h));
    }
}

// =====================================================================
// Kernel A3: BsT transpose + split
// =====================================================================
__global__ void k_bsmall(const float* __restrict__ Bm)
{
    const int idx = blockIdx.x * blockDim.x + threadIdx.x;
    if (idx >= DOUT * ER) return;
    const int o = idx >> 6;
    const int k = idx & 63;
    const float v = Bm[(size_t)(k >> 3) * DOUT * RANK + (size_t)o * RANK + (k & 7)];
    const __nv_bfloat16 h = __float2bfloat16(v);
    g_Bsh[(size_t)o * ER + k] = h;
    g_Bsl[(size_t)o * ER + k] = __float2bfloat16(v - __bfloat162float(h));
}

// =====================================================================
// Kernel B: mma.sync bf16 GEMM  out = x@Wf^T + bf + hp@BsT^T
//   tile 128x128, BK=32, 8 warps (2m x 4n), warp tile 64x32.
//   3-term bf16 emulation; cp.async double-buffered.
//   SMEM per stage: Ah,Al,Bh,Bl each 128 rows x 80B (64B data).
// =====================================================================
#define NCH      66        // 64 main K-chunks + 2 LoRA chunks
#define ROWB     80        // smem row stride (bytes)
#define TILE_B   (128*ROWB)     // 10240
#define STAGE_B  (4*TILE_B)     // 40960
#define SMEM_GB  (2*STAGE_B)    // 81920

struct ChunkSrc {
    const __nv_bfloat16 *ah, *al, *bh, *bl;
    int stride;
};

__device__ __forceinline__ void stage_load(uint32_t s_stage, const ChunkSrc& cs, int tid)
{
#pragma unroll
    for (int i = 0; i < 2; i++) {
        const int idx = tid + i * 256;
        const int row = idx >> 2;
        const int q   = idx & 3;
        const uint32_t so = (uint32_t)(row * ROWB + q * 16);
        const size_t go = (size_t)row * cs.stride + q * 8;
        CP16(s_stage + so,              cs.ah + go);
        CP16(s_stage + TILE_B + so,     cs.al + go);
        CP16(s_stage + 2 * TILE_B + so, cs.bh + go);
        CP16(s_stage + 3 * TILE_B + so, cs.bl + go);
    }
}

__global__ __launch_bounds__(256, 1)
void k_gemm_mma(const float* __restrict__ bfv, float* __restrict__ out)
{
    extern __shared__ __align__(128) char sm[];
    const uint32_t smem_base = smem_u32(sm);

    const int tid  = threadIdx.x;
    const int wid  = tid >> 5;
    const int lane = tid & 31;
    const int m0 = blockIdx.y * 128;
    const int n0 = blockIdx.x * 128;
    const int warp_m = (wid & 1) * 64;
    const int warp_n = (wid >> 1) * 32;

    // ldmatrix per-lane offsets
    const uint32_t a_off = (uint32_t)((warp_m + (lane & 15)) * ROWB + (lane >> 4) * 16);
    const uint32_t b_off = (uint32_t)((warp_n + (lane & 7) + ((lane >> 4) << 3)) * ROWB
                                      + ((lane >> 3) & 1) * 16);

    float acc[4][4][4];
#pragma unroll
    for (int mf = 0; mf < 4; mf++)
#pragma unroll
        for (int nf = 0; nf < 4; nf++)
#pragma unroll
            for (int r = 0; r < 4; r++) acc[mf][nf][r] = 0.f;

    auto make_src = [&](int c) -> ChunkSrc {
        ChunkSrc cs;
        if (c < 64) {
            cs.ah = g_xh + (size_t)m0 * DIN + c * 32;
            cs.al = g_xl + (size_t)m0 * DIN + c * 32;
            cs.bh = g_Wh + (size_t)n0 * DIN + c * 32;
            cs.bl = g_Wl + (size_t)n0 * DIN + c * 32;
            cs.stride = DIN;
        } else {
            const int kk = (c - 64) * 32;
            cs.ah = g_hph + (size_t)m0 * ER + kk;
            cs.al = g_hpl + (size_t)m0 * ER + kk;
            cs.bh = g_Bsh + (size_t)n0 * ER + kk;
            cs.bl = g_Bsl + (size_t)n0 * ER + kk;
            cs.stride = ER;
        }
        return cs;
    };

    {
        ChunkSrc cs = make_src(0);
        stage_load(smem_base, cs, tid);
        CP_COMMIT();
    }

    for (int c = 0; c < NCH; c++) {
        const uint32_t s_cur = smem_base + (uint32_t)(c & 1) * STAGE_B;
        if (c + 1 < NCH) {
            ChunkSrc cs = make_src(c + 1);
            stage_load(smem_base + (uint32_t)((c + 1) & 1) * STAGE_B, cs, tid);
            CP_COMMIT();
            CP_WAIT(1);
        } else {
            CP_WAIT(0);
        }
        __syncthreads();

#pragma unroll
        for (int ks = 0; ks < 2; ks++) {
            uint32_t ah[4][4], al[4][4], bh[4][2], bl[4][2];
#pragma unroll
            for (int mf = 0; mf < 4; mf++) {
                const uint32_t ad = s_cur + a_off + (uint32_t)(mf * 16 * ROWB + ks * 32);
                LDSM4(ah[mf], ad);
                LDSM4(al[mf], ad + TILE_B);
            }
#pragma unroll
            for (int ng = 0; ng < 2; ng++) {
                const uint32_t bd = s_cur + 2 * TILE_B + b_off
                                  + (uint32_t)(ng * 16 * ROWB + ks * 32);
                uint32_t r[4];
                LDSM4(r, bd);
                bh[2*ng][0] = r[0]; bh[2*ng][1] = r[1];
                bh[2*ng+1][0] = r[2]; bh[2*ng+1][1] = r[3];
                LDSM4(r, bd + TILE_B);
                bl[2*ng][0] = r[0]; bl[2*ng][1] = r[1];
                bl[2*ng+1][0] = r[2]; bl[2*ng+1][1] = r[3];
            }
#pragma unroll
            for (int mf = 0; mf < 4; mf++)
#pragma unroll
                for (int nf = 0; nf < 4; nf++) {
                    MMA16816(acc[mf][nf], ah[mf], bh[nf]);
                    MMA16816(acc[mf][nf], ah[mf], bl[nf]);
                    MMA16816(acc[mf][nf], al[mf], bh[nf]);
                }
        }
        __syncthreads();
    }

    // ---- epilogue: acc -> gmem (+bias)
    float2 bias[4];
#pragma unroll
    for (int nf = 0; nf < 4; nf++) {
        const int n = n0 + warp_n + nf * 8 + 2 * (lane & 3);
        bias[nf] = *(const float2*)(bfv + n);
    }
    const int mrow = m0 + warp_m + (lane >> 2);
    const int ncol = n0 + warp_n + 2 * (lane & 3);
#pragma unroll
    for (int mf = 0; mf < 4; mf++) {
#pragma unroll
        for (int nf = 0; nf < 4; nf++) {
            float* p0 = out + (size_t)(mrow + mf * 16) * DOUT + ncol + nf * 8;
            float* p1 = p0 + 8 * DOUT;
            float2 v0 = {acc[mf][nf][0] + bias[nf].x, acc[mf][nf][1] + bias[nf].y};
            float2 v1 = {acc[mf][nf][2] + bias[nf].x, acc[mf][nf][3] + bias[nf].y};
            *(float2*)p0 = v0;
            *(float2*)p1 = v1;
        }
    }
}

// =====================================================================
// launch
// =====================================================================
extern "C" void kernel_launch(void* const* d_in, const int* in_sizes, int n_in,
                              void* d_out, int out_size)
{
    const float* x  = (const float*)d_in[0];
    const float* Wf = (const float*)d_in[1];
    const float* bf = (const float*)d_in[2];
    const float* Wr = (const float*)d_in[3];
    const float* br = (const float*)d_in[4];
    const float* A  = (const float*)d_in[5];
    const float* Bm = (const float*)d_in[6];
    float* out = (float*)d_out;

    const int write_w = (out_size >= MAIN_OUT + W_OUT) ? 1 : 0;

    __nv_bfloat16 *xh, *xl, *wh, *wl;
    cudaGetSymbolAddress((void**)&xh, g_xh);
    cudaGetSymbolAddress((void**)&xl, g_xl);
    cudaGetSymbolAddress((void**)&wh, g_Wh);
    cudaGetSymbolAddress((void**)&wl, g_Wl);

    const int shA = (A_TOKENS + HR) * A_STR * (int)sizeof(float);
    cudaFuncSetAttribute(k_hraw, cudaFuncAttributeMaxDynamicSharedMemorySize, shA);
    cudaFuncSetAttribute(k_gemm_mma, cudaFuncAttributeMaxDynamicSharedMemorySize, SMEM_GB);

    k_split<<<(M_ * DIN / 4 + 255) / 256, 256>>>(x, xh, xl, M_ * DIN / 4);
    k_split<<<(DOUT * DIN / 4 + 255) / 256, 256>>>(Wf, wh, wl, DOUT * DIN / 4);
    k_hraw<<<M_ / A_TOKENS, 256, shA>>>(x, Wr, A);
    k_bsmall<<<(DOUT * ER + 255) / 256, 256>>>(Bm);
    k_softmax<<<(M_ + 255) / 256, 256>>>(br, out + MAIN_OUT, write_w);
    k_gemm_mma<<<dim3(DOUT / 128, M_ / 128), 256, SMEM_GB>>>(bf, out);
}

// round 4
// speedup vs baseline: 4.0602x; 1.7535x over previous
#include <cuda_runtime.h>
#include <cuda_fp16.h>
#include <cstdint>

// ---------------- problem constants ----------------
#define E_      8
#define DIN     2048
#define DOUT    2048
#define RANK    8
#define ER      64
#define M_      8192
#define HR      72
#define MAIN_OUT (M_*DOUT)
#define W_OUT    (M_*E_)

// ---------------- scratch (device globals) ----------------
__device__ __align__(16) float  g_hraw[(size_t)M_ * HR];
__device__ __align__(16) __half g_xh[(size_t)M_ * DIN];
__device__ __align__(16) __half g_Wh[(size_t)DOUT * DIN];
__device__ __align__(16) __half g_hph[(size_t)M_ * ER];
__device__ __align__(16) __half g_Bsh[(size_t)DOUT * ER];

// ---------------- PTX helpers (baseline sm_80-class only) ----------------
__device__ __forceinline__ uint32_t smem_u32(const void* p) {
    uint32_t a;
    asm("{ .reg .u64 t; cvta.to.shared.u64 t, %1; cvt.u32.u64 %0, t; }" : "=r"(a) : "l"(p));
    return a;
}
#define CP16(saddr, gptr) \
    asm volatile("cp.async.cg.shared.global [%0], [%1], 16;" :: "r"(saddr), "l"(gptr))
#define CP_COMMIT() asm volatile("cp.async.commit_group;" ::: "memory")
#define CP_WAIT(n)  asm volatile("cp.async.wait_group %0;" :: "n"(n) : "memory")

#define LDSM4(r, a) \
    asm volatile("ldmatrix.sync.aligned.m8n8.x4.shared.b16 {%0,%1,%2,%3}, [%4];" \
        : "=r"((r)[0]), "=r"((r)[1]), "=r"((r)[2]), "=r"((r)[3]) : "r"(a))

#define MMA16816(d, a, b) \
    asm volatile("mma.sync.aligned.m16n8k16.row.col.f32.f16.f16.f32 " \
        "{%0,%1,%2,%3}, {%4,%5,%6,%7}, {%8,%9}, {%0,%1,%2,%3};" \
        : "+f"((d)[0]), "+f"((d)[1]), "+f"((d)[2]), "+f"((d)[3]) \
        : "r"((a)[0]), "r"((a)[1]), "r"((a)[2]), "r"((a)[3]), \
          "r"((b)[0]), "r"((b)[1]))

// =====================================================================
// Kernel: convert fp32 -> fp16
// =====================================================================
__global__ void k_cvt(const float* __restrict__ s, __half* __restrict__ h, int n4)
{
    const int i = blockIdx.x * blockDim.x + threadIdx.x;
    if (i >= n4) return;
    const float4 v = ((const float4*)s)[i];
    __half2 a = __floats2half2_rn(v.x, v.y);
    __half2 b = __floats2half2_rn(v.z, v.w);
    ((__half2*)h)[2*i]   = a;
    ((__half2*)h)[2*i+1] = b;
}

// =====================================================================
// Kernel A: hraw = x @ concat(Wr, A)^T  (fp32 SIMT, exact router path)
// =====================================================================
#define A_TOKENS 32
#define A_CHUNK  128
#define A_STR    132

__global__ __launch_bounds__(256)
void k_hraw(const float* __restrict__ x,
            const float* __restrict__ Wr,
            const float* __restrict__ A)
{
    extern __shared__ float sh[];
    float* xs  = sh;
    float* as_ = sh + A_TOKENS * A_STR;

    const int tid = threadIdx.x;
    const int t0  = blockIdx.x * A_TOKENS;
    const int tok = tid >> 3;
    const int jg  = tid & 7;

    float acc[9];
#pragma unroll
    for (int j = 0; j < 9; j++) acc[j] = 0.f;

    for (int dc = 0; dc < DIN; dc += A_CHUNK) {
        {
            const int r  = tid >> 3;
            const int c4 = tid & 7;
            const float* src = x + (size_t)(t0 + r) * DIN + dc;
#pragma unroll
            for (int i = 0; i < 4; i++) {
                float4 v = *(const float4*)(src + (c4 + i * 8) * 4);
                *(float4*)(xs + r * A_STR + (c4 + i * 8) * 4) = v;
            }
        }
#pragma unroll
        for (int i = 0; i < 9; i++) {
            const int l  = tid + i * 256;
            const int r  = l >> 5;
            const int c4 = l & 31;
            const float* src = (r < E_) ? (Wr + (size_t)r * DIN)
                                        : (A  + (size_t)(r - E_) * DIN);
            float4 v = *(const float4*)(src + dc + c4 * 4);
            *(float4*)(as_ + r * A_STR + c4 * 4) = v;
        }
        __syncthreads();

        const float* xrow = xs + tok * A_STR;
#pragma unroll 2
        for (int d4 = 0; d4 < A_CHUNK / 4; d4++) {
            const float4 xv = *(const float4*)(xrow + d4 * 4);
#pragma unroll
            for (int j = 0; j < 9; j++) {
                const float4 av = *(const float4*)(as_ + (jg * 9 + j) * A_STR + d4 * 4);
                acc[j] = fmaf(av.x, xv.x, acc[j]);
                acc[j] = fmaf(av.y, xv.y, acc[j]);
                acc[j] = fmaf(av.z, xv.z, acc[j]);
                acc[j] = fmaf(av.w, xv.w, acc[j]);
            }
        }
        __syncthreads();
    }

    const int gt = t0 + tok;
#pragma unroll
    for (int j = 0; j < 9; j++)
        g_hraw[(size_t)gt * HR + jg * 9 + j] = acc[j];
}

// =====================================================================
// Kernel A2: softmax (fp32, exact) + fold weights -> hp fp16, write w
// =====================================================================
__global__ void k_softmax(const float* __restrict__ br,
                          float* __restrict__ wout, int write_w)
{
    const int t = blockIdx.x * blockDim.x + threadIdx.x;
    if (t >= M_) return;
    const float* row = g_hraw + (size_t)t * HR;

    float l[E_];
    float mx = -1e30f;
#pragma unroll
    for (int e = 0; e < E_; e++) { l[e] = row[e] + br[e]; mx = fmaxf(mx, l[e]); }
    float s = 0.f;
#pragma unroll
    for (int e = 0; e < E_; e++) { l[e] = expf(l[e] - mx); s += l[e]; }
    const float inv = 1.f / s;
#pragma unroll
    for (int e = 0; e < E_; e++) l[e] *= inv;

    if (write_w) {
#pragma unroll
        for (int e = 0; e < E_; e++) wout[(size_t)t * E_ + e] = l[e];
    }
#pragma unroll
    for (int k = 0; k < ER; k += 2) {
        const float v0 = l[(k    ) >> 3] * row[E_ + k];
        const float v1 = l[(k + 1) >> 3] * row[E_ + k + 1];
        ((__half2*)(g_hph + (size_t)t * ER))[k >> 1] = __floats2half2_rn(v0, v1);
    }
}

// =====================================================================
// Kernel A3: BsT transpose -> fp16
// =====================================================================
__global__ void k_bsmall(const float* __restrict__ Bm)
{
    const int idx = blockIdx.x * blockDim.x + threadIdx.x;
    if (idx >= DOUT * ER) return;
    const int o = idx >> 6;
    const int k = idx & 63;
    const float v = Bm[(size_t)(k >> 3) * DOUT * RANK + (size_t)o * RANK + (k & 7)];
    g_Bsh[(size_t)o * ER + k] = __float2half_rn(v);
}

// =====================================================================
// Kernel B: mma.sync fp16 GEMM  out = x@Wf^T + bf + hp@BsT^T
//   tile 128x128, BK=64, 33 chunks (32 main + 1 LoRA).
//   4-stage cp.async ring, prefetch distance 2, one barrier per chunk.
//   8 warps (2m x 4n), warp tile 64x32, acc fp32.
// =====================================================================
#define NCH      33
#define ROWB     144            // 128B data + 16B pad (conflict-free ldmatrix)
#define TILE_B   (128*ROWB)     // 18432
#define STAGE_B  (2*TILE_B)     // 36864 (A then B)
#define NSTAGE   4
#define SMEM_GB  (NSTAGE*STAGE_B)   // 147456

__device__ __forceinline__ void stage_load(uint32_t s_stage, int c, int m0, int n0, int tid)
{
    const __half *ga, *gb;
    int stride;
    if (c < 32) {
        ga = g_xh + (size_t)m0 * DIN + c * 64;
        gb = g_Wh + (size_t)n0 * DIN + c * 64;
        stride = DIN;
    } else {
        ga = g_hph + (size_t)m0 * ER;
        gb = g_Bsh + (size_t)n0 * ER;
        stride = ER;
    }
    // A: 128 rows x 128B -> slots 0..1023 ; B likewise
#pragma unroll
    for (int i = 0; i < 4; i++) {
        const int idx = tid + i * 256;
        const int row = idx >> 3;
        const int q   = idx & 7;
        const uint32_t so = (uint32_t)(row * ROWB + q * 16);
        const size_t go = (size_t)row * stride + q * 8;
        CP16(s_stage + so,          ga + go);
        CP16(s_stage + TILE_B + so, gb + go);
    }
}

__global__ __launch_bounds__(256, 1)
void k_gemm_mma(const float* __restrict__ bfv, float* __restrict__ out)
{
    extern __shared__ __align__(128) char sm[];
    const uint32_t smem_base = smem_u32(sm);

    const int tid  = threadIdx.x;
    const int wid  = tid >> 5;
    const int lane = tid & 31;
    const int m0 = blockIdx.y * 128;
    const int n0 = blockIdx.x * 128;
    const int warp_m = (wid & 1) * 64;
    const int warp_n = (wid >> 1) * 32;

    const uint32_t a_off = (uint32_t)((warp_m + (lane & 15)) * ROWB + (lane >> 4) * 16);
    const uint32_t b_off = (uint32_t)((warp_n + (lane & 7) + ((lane >> 4) << 3)) * ROWB
                                      + ((lane >> 3) & 1) * 16);

    float acc[4][4][4];
#pragma unroll
    for (int mf = 0; mf < 4; mf++)
#pragma unroll
        for (int nf = 0; nf < 4; nf++)
#pragma unroll
            for (int r = 0; r < 4; r++) acc[mf][nf][r] = 0.f;

    // prologue: chunks 0 and 1
    stage_load(smem_base, 0, m0, n0, tid);
    CP_COMMIT();
    stage_load(smem_base + STAGE_B, 1, m0, n0, tid);
    CP_COMMIT();

    for (int c = 0; c < NCH; c++) {
        if (c + 2 < NCH)
            stage_load(smem_base + (uint32_t)((c + 2) & 3) * STAGE_B, c + 2, m0, n0, tid);
        CP_COMMIT();
        CP_WAIT(2);
        __syncthreads();

        const uint32_t s_cur = smem_base + (uint32_t)(c & 3) * STAGE_B;
#pragma unroll
        for (int ks = 0; ks < 4; ks++) {
            uint32_t ah[4][4], bh[4][2];
#pragma unroll
            for (int mf = 0; mf < 4; mf++)
                LDSM4(ah[mf], s_cur + a_off + (uint32_t)(mf * 16 * ROWB + ks * 32));
#pragma unroll
            for (int ng = 0; ng < 2; ng++) {
                uint32_t r[4];
                LDSM4(r, s_cur + TILE_B + b_off + (uint32_t)(ng * 16 * ROWB + ks * 32));
                bh[2*ng][0]   = r[0]; bh[2*ng][1]   = r[1];
                bh[2*ng+1][0] = r[2]; bh[2*ng+1][1] = r[3];
            }
#pragma unroll
            for (int mf = 0; mf < 4; mf++)
#pragma unroll
                for (int nf = 0; nf < 4; nf++)
                    MMA16816(acc[mf][nf], ah[mf], bh[nf]);
        }
    }

    // ---- epilogue: acc -> gmem (+bias)
    float2 bias[4];
#pragma unroll
    for (int nf = 0; nf < 4; nf++) {
        const int n = n0 + warp_n + nf * 8 + 2 * (lane & 3);
        bias[nf] = *(const float2*)(bfv + n);
    }
    const int mrow = m0 + warp_m + (lane >> 2);
    const int ncol = n0 + warp_n + 2 * (lane & 3);
#pragma unroll
    for (int mf = 0; mf < 4; mf++) {
#pragma unroll
        for (int nf = 0; nf < 4; nf++) {
            float* p0 = out + (size_t)(mrow + mf * 16) * DOUT + ncol + nf * 8;
            float* p1 = p0 + 8 * DOUT;
            float2 v0 = {acc[mf][nf][0] + bias[nf].x, acc[mf][nf][1] + bias[nf].y};
            float2 v1 = {acc[mf][nf][2] + bias[nf].x, acc[mf][nf][3] + bias[nf].y};
            *(float2*)p0 = v0;
            *(float2*)p1 = v1;
        }
    }
}

// =====================================================================
// launch
// =====================================================================
extern "C" void kernel_launch(void* const* d_in, const int* in_sizes, int n_in,
                              void* d_out, int out_size)
{
    const float* x  = (const float*)d_in[0];
    const float* Wf = (const float*)d_in[1];
    const float* bf = (const float*)d_in[2];
    const float* Wr = (const float*)d_in[3];
    const float* br = (const float*)d_in[4];
    const float* A  = (const float*)d_in[5];
    const float* Bm = (const float*)d_in[6];
    float* out = (float*)d_out;

    const int write_w = (out_size >= MAIN_OUT + W_OUT) ? 1 : 0;

    __half *xh, *wh;
    cudaGetSymbolAddress((void**)&xh, g_xh);
    cudaGetSymbolAddress((void**)&wh, g_Wh);

    const int shA = (A_TOKENS + HR) * A_STR * (int)sizeof(float);
    cudaFuncSetAttribute(k_hraw, cudaFuncAttributeMaxDynamicSharedMemorySize, shA);
    cudaFuncSetAttribute(k_gemm_mma, cudaFuncAttributeMaxDynamicSharedMemorySize, SMEM_GB);

    k_cvt<<<(M_ * DIN / 4 + 255) / 256, 256>>>(x, xh, M_ * DIN / 4);
    k_cvt<<<(DOUT * DIN / 4 + 255) / 256, 256>>>(Wf, wh, DOUT * DIN / 4);
    k_hraw<<<M_ / A_TOKENS, 256, shA>>>(x, Wr, A);
    k_bsmall<<<(DOUT * ER + 255) / 256, 256>>>(Bm);
    k_softmax<<<(M_ + 255) / 256, 256>>>(br, out + MAIN_OUT, write_w);
    k_gemm_mma<<<dim3(DOUT / 128, M_ / 128), 256, SMEM_GB>>>(bf, out);
}

// round 7
// speedup vs baseline: 4.5048x; 1.1095x over previous
#include <cuda_runtime.h>
#include <cuda_fp16.h>
#include <cstdint>

// ---------------- problem constants ----------------
#define E_      8
#define DIN     2048
#define DOUT    2048
#define RANK    8
#define ER      64
#define M_      8192
#define HR      72
#define MAIN_OUT (M_*DOUT)
#define W_OUT    (M_*E_)

// ---------------- scratch (device globals) ----------------
__device__ __align__(16) __half g_xh[(size_t)M_ * DIN];
__device__ __align__(16) __half g_Wh[(size_t)DOUT * DIN];
__device__ __align__(16) __half g_hph[(size_t)M_ * ER];
__device__ __align__(16) __half g_Bsh[(size_t)DOUT * ER];

// ---------------- PTX helpers (baseline sm_80-class only) ----------------
__device__ __forceinline__ uint32_t smem_u32(const void* p) {
    uint32_t a;
    asm("{ .reg .u64 t; cvta.to.shared.u64 t, %1; cvt.u32.u64 %0, t; }" : "=r"(a) : "l"(p));
    return a;
}
#define CP16(saddr, gptr) \
    asm volatile("cp.async.cg.shared.global [%0], [%1], 16;" :: "r"(saddr), "l"(gptr))
#define CP_COMMIT() asm volatile("cp.async.commit_group;" ::: "memory")
#define CP_WAIT(n)  asm volatile("cp.async.wait_group %0;" :: "n"(n) : "memory")

#define LDSM4(r, a) \
    asm volatile("ldmatrix.sync.aligned.m8n8.x4.shared.b16 {%0,%1,%2,%3}, [%4];" \
        : "=r"((r)[0]), "=r"((r)[1]), "=r"((r)[2]), "=r"((r)[3]) : "r"(a))

#define MMA16816(d, a, b) \
    asm volatile("mma.sync.aligned.m16n8k16.row.col.f32.f16.f16.f32 " \
        "{%0,%1,%2,%3}, {%4,%5,%6,%7}, {%8,%9}, {%0,%1,%2,%3};" \
        : "+f"((d)[0]), "+f"((d)[1]), "+f"((d)[2]), "+f"((d)[3]) \
        : "r"((a)[0]), "r"((a)[1]), "r"((a)[2]), "r"((a)[3]), \
          "r"((b)[0]), "r"((b)[1]))

// =====================================================================
// Kernel: convert fp32 -> fp16 (used for Wf only; x is fused into k_hraw)
// =====================================================================
__global__ void k_cvt(const float* __restrict__ s, __half* __restrict__ h, int n4)
{
    const int i = blockIdx.x * blockDim.x + threadIdx.x;
    if (i >= n4) return;
    const float4 v = ((const float4*)s)[i];
    ((__half2*)h)[2*i]   = __floats2half2_rn(v.x, v.y);
    ((__half2*)h)[2*i+1] = __floats2half2_rn(v.z, v.w);
}

// =====================================================================
// Kernel A (fused): per 32-token block
//   - stage x chunks, convert+write g_xh (fp16)
//   - hraw = x @ concat(Wr, A)^T  (fp32)
//   - softmax over 8 logits, write w, fold weights -> g_hph (fp16)
// =====================================================================
#define A_TOKENS 32
#define A_CHUNK  128
#define A_STR    132
#define HB_STR   76

__global__ __launch_bounds__(256)
void k_hraw(const float* __restrict__ x,
            const float* __restrict__ Wr,
            const float* __restrict__ A,
            const float* __restrict__ br,
            float* __restrict__ wout, int write_w)
{
    extern __shared__ float sh[];
    float* xs  = sh;                       // [A_TOKENS][A_STR]
    float* as_ = sh + A_TOKENS * A_STR;    // [HR][A_STR]

    const int tid = threadIdx.x;
    const int t0  = blockIdx.x * A_TOKENS;
    const int tok = tid >> 3;
    const int jg  = tid & 7;

    float acc[9];
#pragma unroll
    for (int j = 0; j < 9; j++) acc[j] = 0.f;

    for (int dc = 0; dc < DIN; dc += A_CHUNK) {
        {
            const int r  = tid >> 3;
            const int c4 = tid & 7;
            const float* src = x + (size_t)(t0 + r) * DIN + dc;
#pragma unroll
            for (int i = 0; i < 4; i++) {
                float4 v = *(const float4*)(src + (c4 + i * 8) * 4);
                *(float4*)(xs + r * A_STR + (c4 + i * 8) * 4) = v;
            }
        }
#pragma unroll
        for (int i = 0; i < 9; i++) {
            const int l  = tid + i * 256;
            const int r  = l >> 5;
            const int c4 = l & 31;
            const float* src = (r < E_) ? (Wr + (size_t)r * DIN)
                                        : (A  + (size_t)(r - E_) * DIN);
            float4 v = *(const float4*)(src + dc + c4 * 4);
            *(float4*)(as_ + r * A_STR + c4 * 4) = v;
        }
        __syncthreads();

        // fused: convert staged x chunk to fp16 and write g_xh
#pragma unroll
        for (int i = 0; i < 8; i++) {
            const int idx2 = tid + i * 256;          // half2 index, 0..2047
            const int r = idx2 >> 6;
            const int c = (idx2 & 63) * 2;
            const __half2 hv = __floats2half2_rn(xs[r * A_STR + c], xs[r * A_STR + c + 1]);
            *(__half2*)(g_xh + (size_t)(t0 + r) * DIN + dc + c) = hv;
        }

        const float* xrow = xs + tok * A_STR;
#pragma unroll 2
        for (int d4 = 0; d4 < A_CHUNK / 4; d4++) {
            const float4 xv = *(const float4*)(xrow + d4 * 4);
#pragma unroll
            for (int j = 0; j < 9; j++) {
                const float4 av = *(const float4*)(as_ + (jg * 9 + j) * A_STR + d4 * 4);
                acc[j] = fmaf(av.x, xv.x, acc[j]);
                acc[j] = fmaf(av.y, xv.y, acc[j]);
                acc[j] = fmaf(av.z, xv.z, acc[j]);
                acc[j] = fmaf(av.w, xv.w, acc[j]);
            }
        }
        __syncthreads();
    }

    // stash hraw rows in smem, then softmax+fold per token
    float* hb = sh;                        // [A_TOKENS][HB_STR]
#pragma unroll
    for (int j = 0; j < 9; j++)
        hb[tok * HB_STR + jg * 9 + j] = acc[j];
    __syncthreads();

    if (tid < A_TOKENS) {
        const int t = t0 + tid;
        const float* row = hb + tid * HB_STR;
        float l[E_];
        float mx = -1e30f;
#pragma unroll
        for (int e = 0; e < E_; e++) { l[e] = row[e] + br[e]; mx = fmaxf(mx, l[e]); }
        float s = 0.f;
#pragma unroll
        for (int e = 0; e < E_; e++) { l[e] = expf(l[e] - mx); s += l[e]; }
        const float inv = 1.f / s;
#pragma unroll
        for (int e = 0; e < E_; e++) l[e] *= inv;

        if (write_w) {
            float4* wp = (float4*)(wout + (size_t)t * E_);
            wp[0] = make_float4(l[0], l[1], l[2], l[3]);
            wp[1] = make_float4(l[4], l[5], l[6], l[7]);
        }
#pragma unroll
        for (int k = 0; k < ER; k += 2) {
            const float v0 = l[(k    ) >> 3] * row[E_ + k];
            const float v1 = l[(k + 1) >> 3] * row[E_ + k + 1];
            ((__half2*)(g_hph + (size_t)t * ER))[k >> 1] = __floats2half2_rn(v0, v1);
        }
    }
}

// =====================================================================
// Kernel A3: BsT transpose -> fp16
// =====================================================================
__global__ void k_bsmall(const float* __restrict__ Bm)
{
    const int idx = blockIdx.x * blockDim.x + threadIdx.x;
    if (idx >= DOUT * ER) return;
    const int o = idx >> 6;
    const int k = idx & 63;
    const float v = Bm[(size_t)(k >> 3) * DOUT * RANK + (size_t)o * RANK + (k & 7)];
    g_Bsh[(size_t)o * ER + k] = __float2half_rn(v);
}

// =====================================================================
// Kernel B: mma.sync fp16 GEMM  out = x@Wf^T + bf + hp@BsT^T
//   tile 128x128, BK=32, 66 chunks (64 main + 2 LoRA).
//   4-stage cp.async ring, prefetch distance 2, one barrier per chunk.
//   8 warps (2m x 4n), warp tile 64x32. 80KB smem -> 2 CTAs/SM.
// =====================================================================
#define NCH      66
#define ROWB     80             // 64B data + 16B pad
#define TILE_B   (128*ROWB)     // 10240
#define STAGE_B  (2*TILE_B)     // 20480 (A then B)
#define NSTAGE   4
#define SMEM_GB  (NSTAGE*STAGE_B)   // 81920

__device__ __forceinline__ void stage_load(uint32_t s_stage, int c, int m0, int n0, int tid)
{
    const __half *ga, *gb;
    int stride;
    if (c < 64) {
        ga = g_xh + (size_t)m0 * DIN + c * 32;
        gb = g_Wh + (size_t)n0 * DIN + c * 32;
        stride = DIN;
    } else {
        const int kk = (c - 64) * 32;
        ga = g_hph + (size_t)m0 * ER + kk;
        gb = g_Bsh + (size_t)n0 * ER + kk;
        stride = ER;
    }
#pragma unroll
    for (int i = 0; i < 2; i++) {
        const int idx = tid + i * 256;
        const int row = idx >> 2;
        const int q   = idx & 3;
        const uint32_t so = (uint32_t)(row * ROWB + q * 16);
        const size_t go = (size_t)row * stride + q * 8;
        CP16(s_stage + so,          ga + go);
        CP16(s_stage + TILE_B + so, gb + go);
    }
}

__global__ __launch_bounds__(256, 2)
void k_gemm_mma(const float* __restrict__ bfv, float* __restrict__ out)
{
    extern __shared__ __align__(128) char sm[];
    const uint32_t smem_base = smem_u32(sm);

    const int tid  = threadIdx.x;
    const int wid  = tid >> 5;
    const int lane = tid & 31;
    const int m0 = blockIdx.y * 128;
    const int n0 = blockIdx.x * 128;
    const int warp_m = (wid & 1) * 64;
    const int warp_n = (wid >> 1) * 32;

    const uint32_t a_off = (uint32_t)((warp_m + (lane & 15)) * ROWB + (lane >> 4) * 16);
    const uint32_t b_off = (uint32_t)((warp_n + (lane & 7) + ((lane >> 4) << 3)) * ROWB
                                      + ((lane >> 3) & 1) * 16);

    float acc[4][4][4];
#pragma unroll
    for (int mf = 0; mf < 4; mf++)
#pragma unroll
        for (int nf = 0; nf < 4; nf++)
#pragma unroll
            for (int r = 0; r < 4; r++) acc[mf][nf][r] = 0.f;

    stage_load(smem_base, 0, m0, n0, tid);
    CP_COMMIT();
    stage_load(smem_base + STAGE_B, 1, m0, n0, tid);
    CP_COMMIT();

    for (int c = 0; c < NCH; c++) {
        if (c + 2 < NCH)
            stage_load(smem_base + (uint32_t)((c + 2) & 3) * STAGE_B, c + 2, m0, n0, tid);
        CP_COMMIT();
        CP_WAIT(2);
        __syncthreads();

        const uint32_t s_cur = smem_base + (uint32_t)(c & 3) * STAGE_B;
#pragma unroll
        for (int ks = 0; ks < 2; ks++) {
            uint32_t ah[4][4], bh[4][2];
#pragma unroll
            for (int mf = 0; mf < 4; mf++)
                LDSM4(ah[mf], s_cur + a_off + (uint32_t)(mf * 16 * ROWB + ks * 32));
#pragma unroll
            for (int ng = 0; ng < 2; ng++) {
                uint32_t r[4];
                LDSM4(r, s_cur + TILE_B + b_off + (uint32_t)(ng * 16 * ROWB + ks * 32));
                bh[2*ng][0]   = r[0]; bh[2*ng][1]   = r[1];
                bh[2*ng+1][0] = r[2]; bh[2*ng+1][1] = r[3];
            }
#pragma unroll
            for (int mf = 0; mf < 4; mf++)
#pragma unroll
                for (int nf = 0; nf < 4; nf++)
                    MMA16816(acc[mf][nf], ah[mf], bh[nf]);
        }
    }

    // ---- epilogue: acc -> gmem (+bias)
    float2 bias[4];
#pragma unroll
    for (int nf = 0; nf < 4; nf++) {
        const int n = n0 + warp_n + nf * 8 + 2 * (lane & 3);
        bias[nf] = *(const float2*)(bfv + n);
    }
    const int mrow = m0 + warp_m + (lane >> 2);
    const int ncol = n0 + warp_n + 2 * (lane & 3);
#pragma unroll
    for (int mf = 0; mf < 4; mf++) {
#pragma unroll
        for (int nf = 0; nf < 4; nf++) {
            float* p0 = out + (size_t)(mrow + mf * 16) * DOUT + ncol + nf * 8;
            float* p1 = p0 + 8 * DOUT;
            float2 v0 = {acc[mf][nf][0] + bias[nf].x, acc[mf][nf][1] + bias[nf].y};
            float2 v1 = {acc[mf][nf][2] + bias[nf].x, acc[mf][nf][3] + bias[nf].y};
            *(float2*)p0 = v0;
            *(float2*)p1 = v1;
        }
    }
}

// =====================================================================
// launch
// =====================================================================
extern "C" void kernel_launch(void* const* d_in, const int* in_sizes, int n_in,
                              void* d_out, int out_size)
{
    const float* x  = (const float*)d_in[0];
    const float* Wf = (const float*)d_in[1];
    const float* bf = (const float*)d_in[2];
    const float* Wr = (const float*)d_in[3];
    const float* br = (const float*)d_in[4];
    const float* A  = (const float*)d_in[5];
    const float* Bm = (const float*)d_in[6];
    float* out = (float*)d_out;

    const int write_w = (out_size >= MAIN_OUT + W_OUT) ? 1 : 0;

    __half* wh;
    cudaGetSymbolAddress((void**)&wh, g_Wh);

    const int shA = (A_TOKENS + HR) * A_STR * (int)sizeof(float);
    cudaFuncSetAttribute(k_hraw, cudaFuncAttributeMaxDynamicSharedMemorySize, shA);
    cudaFuncSetAttribute(k_gemm_mma, cudaFuncAttributeMaxDynamicSharedMemorySize, SMEM_GB);

    k_cvt<<<(DOUT * DIN / 4 + 255) / 256, 256>>>(Wf, wh, DOUT * DIN / 4);
    k_bsmall<<<(DOUT * ER + 255) / 256, 256>>>(Bm);
    k_hraw<<<M_ / A_TOKENS, 256, shA>>>(x, Wr, A, br, out + MAIN_OUT, write_w);
    k_gemm_mma<<<dim3(DOUT / 128, M_ / 128), 256, SMEM_GB>>>(bf, out);
}

// round 9
// speedup vs baseline: 6.9701x; 1.5473x over previous
#include <cuda_runtime.h>
#include <cuda_fp16.h>
#include <cstdint>

// ---------------- problem constants ----------------
#define E_      8
#define DIN     2048
#define DOUT    2048
#define RANK    8
#define ER      64
#define M_      8192
#define MAIN_OUT (M_*DOUT)
#define W_OUT    (M_*E_)

// ---------------- scratch (device globals) ----------------
__device__ __align__(16) __half g_xh[(size_t)M_ * DIN];
__device__ __align__(16) __half g_Wh[(size_t)DOUT * DIN];
__device__ __align__(16) __half g_hph[(size_t)M_ * ER];
__device__ __align__(16) __half g_Bsh[(size_t)DOUT * ER];
__device__ __align__(16) __half g_Cat[(size_t)80 * DIN];   // rows 0-7 Wr, 8-71 A, 72-79 zero

// ---------------- PTX helpers (baseline sm_80-class only) ----------------
__device__ __forceinline__ uint32_t smem_u32(const void* p) {
    uint32_t a;
    asm("{ .reg .u64 t; cvta.to.shared.u64 t, %1; cvt.u32.u64 %0, t; }" : "=r"(a) : "l"(p));
    return a;
}
#define CP16(saddr, gptr) \
    asm volatile("cp.async.cg.shared.global [%0], [%1], 16;" :: "r"(saddr), "l"(gptr))
#define CP_COMMIT() asm volatile("cp.async.commit_group;" ::: "memory")
#define CP_WAIT(n)  asm volatile("cp.async.wait_group %0;" :: "n"(n) : "memory")

#define LDSM4(r, a) \
    asm volatile("ldmatrix.sync.aligned.m8n8.x4.shared.b16 {%0,%1,%2,%3}, [%4];" \
        : "=r"((r)[0]), "=r"((r)[1]), "=r"((r)[2]), "=r"((r)[3]) : "r"(a))

#define MMA16816(d, a, b) \
    asm volatile("mma.sync.aligned.m16n8k16.row.col.f32.f16.f16.f32 " \
        "{%0,%1,%2,%3}, {%4,%5,%6,%7}, {%8,%9}, {%0,%1,%2,%3};" \
        : "+f"((d)[0]), "+f"((d)[1]), "+f"((d)[2]), "+f"((d)[3]) \
        : "r"((a)[0]), "r"((a)[1]), "r"((a)[2]), "r"((a)[3]), \
          "r"((b)[0]), "r"((b)[1]))

// =====================================================================
// k_cvt: x fp32 -> fp16
// =====================================================================
__global__ void k_cvt(const float* __restrict__ s, __half* __restrict__ h, int n4)
{
    const int i = blockIdx.x * blockDim.x + threadIdx.x;
    if (i >= n4) return;
    const float4 v = ((const float4*)s)[i];
    ((__half2*)h)[2*i]   = __floats2half2_rn(v.x, v.y);
    ((__half2*)h)[2*i+1] = __floats2half2_rn(v.z, v.w);
}

// =====================================================================
// k_prep (fused): Wf->fp16, BsT transpose->fp16, Cat=[Wr;A;0]->fp16
// =====================================================================
#define NW4   (DOUT*DIN/4)     // 1048576
#define NBS   (DOUT*ER)        // 131072
#define NCAT2 (80*DIN/2)       // 81920
#define NPREP (NW4+NBS+NCAT2)

__global__ void k_prep(const float* __restrict__ Wf,
                       const float* __restrict__ Wr,
                       const float* __restrict__ A,
                       const float* __restrict__ Bm)
{
    int i = blockIdx.x * blockDim.x + threadIdx.x;
    if (i < NW4) {
        const float4 v = ((const float4*)Wf)[i];
        ((__half2*)g_Wh)[2*i]   = __floats2half2_rn(v.x, v.y);
        ((__half2*)g_Wh)[2*i+1] = __floats2half2_rn(v.z, v.w);
        return;
    }
    i -= NW4;
    if (i < NBS) {
        const int o = i >> 6;
        const int k = i & 63;
        const float v = Bm[(size_t)(k >> 3) * DOUT * RANK + (size_t)o * RANK + (k & 7)];
        g_Bsh[(size_t)o * ER + k] = __float2half_rn(v);
        return;
    }
    i -= NBS;
    if (i < NCAT2) {
        const int row = i >> 10;
        const int c2  = (i & 1023) * 2;
        float v0 = 0.f, v1 = 0.f;
        if (row < 8)       { v0 = Wr[row * DIN + c2];       v1 = Wr[row * DIN + c2 + 1]; }
        else if (row < 72) { v0 = A[(row - 8) * DIN + c2];  v1 = A[(row - 8) * DIN + c2 + 1]; }
        ((__half2*)g_Cat)[i] = __floats2half2_rn(v0, v1);
    }
}

// =====================================================================
// k_hraw_mma: hraw[8192,72] = xh @ Cat^T via mma.sync, fused softmax:
//   writes w (fp32) and g_hph = l[e]*h (fp16) directly from registers.
//   block = 64 tokens, 4 warps (16 tokens each), BK=64, 32 chunks,
//   4-stage cp.async ring with prefetch distance 2.
// =====================================================================
#define HM_ROWB  144
#define HM_AT    (64*HM_ROWB)        // 9216
#define HM_BT    (80*HM_ROWB)        // 11520
#define HM_STAGE (HM_AT+HM_BT)       // 20736
#define HM_SMEM  (4*HM_STAGE)        // 82944
#define HM_NCH   32

__device__ __forceinline__ void hm_load(uint32_t s, int c, int tb, int tid)
{
#pragma unroll
    for (int i = 0; i < 4; i++) {
        const int idx = tid + i * 128;
        const int row = idx >> 3, q = idx & 7;
        CP16(s + (uint32_t)(row * HM_ROWB + q * 16),
             g_xh + (size_t)(tb + row) * DIN + c * 64 + q * 8);
    }
#pragma unroll
    for (int i = 0; i < 5; i++) {
        const int idx = tid + i * 128;
        const int row = idx >> 3, q = idx & 7;
        CP16(s + HM_AT + (uint32_t)(row * HM_ROWB + q * 16),
             g_Cat + (size_t)row * DIN + c * 64 + q * 8);
    }
}

__global__ __launch_bounds__(128)
void k_hraw_mma(const float* __restrict__ br, float* __restrict__ wout, int write_w)
{
    extern __shared__ __align__(128) char smh[];
    const uint32_t sb = smem_u32(smh);
    const int tid  = threadIdx.x;
    const int wid  = tid >> 5;
    const int lane = tid & 31;
    const int tb   = blockIdx.x * 64;

    const uint32_t a_off = (uint32_t)((wid * 16 + (lane & 15)) * HM_ROWB + (lane >> 4) * 16);
    const uint32_t b_off = (uint32_t)(((lane & 7) + ((lane >> 4) << 3)) * HM_ROWB
                                      + ((lane >> 3) & 1) * 16);

    float acc[9][4];
#pragma unroll
    for (int nf = 0; nf < 9; nf++)
#pragma unroll
        for (int r = 0; r < 4; r++) acc[nf][r] = 0.f;

    hm_load(sb, 0, tb, tid);
    CP_COMMIT();
    hm_load(sb + HM_STAGE, 1, tb, tid);
    CP_COMMIT();

    for (int c = 0; c < HM_NCH; c++) {
        if (c + 2 < HM_NCH)
            hm_load(sb + (uint32_t)((c + 2) & 3) * HM_STAGE, c + 2, tb, tid);
        CP_COMMIT();
        CP_WAIT(2);
        __syncthreads();

        const uint32_t s_cur = sb + (uint32_t)(c & 3) * HM_STAGE;
#pragma unroll
        for (int ks = 0; ks < 4; ks++) {
            uint32_t ah[4], bh[10][2];
            LDSM4(ah, s_cur + a_off + (uint32_t)(ks * 32));
#pragma unroll
            for (int ng = 0; ng < 5; ng++) {
                uint32_t r[4];
                LDSM4(r, s_cur + HM_AT + b_off + (uint32_t)(ng * 16 * HM_ROWB + ks * 32));
                bh[2*ng][0]   = r[0]; bh[2*ng][1]   = r[1];
                bh[2*ng+1][0] = r[2]; bh[2*ng+1][1] = r[3];
            }
#pragma unroll
            for (int nf = 0; nf < 9; nf++)
                MMA16816(acc[nf], ah, bh[nf]);
        }
    }

    // ---- fused epilogue: softmax over cols 0..7, fold into cols 8..71
    const int q  = lane & 3;
    const int r0 = tb + wid * 16 + (lane >> 2);     // row 0 of this thread
    const float b0 = br[2*q], b1 = br[2*q + 1];

    const float a0 = acc[0][0] + b0, a1 = acc[0][1] + b1;   // row r0, logits e=2q,2q+1
    const float c0 = acc[0][2] + b0, c1 = acc[0][3] + b1;   // row r0+8

    float m0 = fmaxf(a0, a1);
    m0 = fmaxf(m0, __shfl_xor_sync(0xffffffffu, m0, 1, 4));
    m0 = fmaxf(m0, __shfl_xor_sync(0xffffffffu, m0, 2, 4));
    float m1 = fmaxf(c0, c1);
    m1 = fmaxf(m1, __shfl_xor_sync(0xffffffffu, m1, 1, 4));
    m1 = fmaxf(m1, __shfl_xor_sync(0xffffffffu, m1, 2, 4));

    const float e00 = __expf(a0 - m0), e01 = __expf(a1 - m0);
    const float e10 = __expf(c0 - m1), e11 = __expf(c1 - m1);
    float s0 = e00 + e01;
    s0 += __shfl_xor_sync(0xffffffffu, s0, 1, 4);
    s0 += __shfl_xor_sync(0xffffffffu, s0, 2, 4);
    float s1 = e10 + e11;
    s1 += __shfl_xor_sync(0xffffffffu, s1, 1, 4);
    s1 += __shfl_xor_sync(0xffffffffu, s1, 2, 4);

    const float p00 = e00 / s0, p01 = e01 / s0;   // own probs row0, e=2q,2q+1
    const float p10 = e10 / s1, p11 = e11 / s1;   // row1

    if (write_w) {
        *(float2*)(wout + (size_t)r0 * E_ + 2*q)       = make_float2(p00, p01);
        *(float2*)(wout + (size_t)(r0 + 8) * E_ + 2*q) = make_float2(p10, p11);
    }

#pragma unroll
    for (int nf = 1; nf < 9; nf++) {
        const int e = nf - 1;
        const int src = (lane & ~3) | (e >> 1);
        const float l0 = __shfl_sync(0xffffffffu, (e & 1) ? p01 : p00, src);
        const float l1 = __shfl_sync(0xffffffffu, (e & 1) ? p11 : p10, src);
        const __half2 h0 = __floats2half2_rn(acc[nf][0] * l0, acc[nf][1] * l0);
        const __half2 h1 = __floats2half2_rn(acc[nf][2] * l1, acc[nf][3] * l1);
        *(__half2*)(g_hph + (size_t)r0 * ER + 8*e + 2*q)       = h0;
        *(__half2*)(g_hph + (size_t)(r0 + 8) * ER + 8*e + 2*q) = h1;
    }
}

// =====================================================================
// Kernel B: mma.sync fp16 GEMM  out = x@Wf^T + bf + hp@BsT^T  (UNCHANGED)
//   tile 128x128, BK=32, 66 chunks. 4-stage ring, distance 2.
//   8 warps (2m x 4n), warp tile 64x32. 80KB smem -> 2 CTAs/SM.
// =====================================================================
#define NCH      66
#define ROWB     80
#define TILE_B   (128*ROWB)
#define STAGE_B  (2*TILE_B)
#define NSTAGE   4
#define SMEM_GB  (NSTAGE*STAGE_B)

__device__ __forceinline__ void stage_load(uint32_t s_stage, int c, int m0, int n0, int tid)
{
    const __half *ga, *gb;
    int stride;
    if (c < 64) {
        ga = g_xh + (size_t)m0 * DIN + c * 32;
        gb = g_Wh + (size_t)n0 * DIN + c * 32;
        stride = DIN;
    } else {
        const int kk = (c - 64) * 32;
        ga = g_hph + (size_t)m0 * ER + kk;
        gb = g_Bsh + (size_t)n0 * ER + kk;
        stride = ER;
    }
#pragma unroll
    for (int i = 0; i < 2; i++) {
        const int idx = tid + i * 256;
        const int row = idx >> 2;
        const int q   = idx & 3;
        const uint32_t so = (uint32_t)(row * ROWB + q * 16);
        const size_t go = (size_t)row * stride + q * 8;
        CP16(s_stage + so,          ga + go);
        CP16(s_stage + TILE_B + so, gb + go);
    }
}

__global__ __launch_bounds__(256, 2)
void k_gemm_mma(const float* __restrict__ bfv, float* __restrict__ out)
{
    extern __shared__ __align__(128) char sm[];
    const uint32_t smem_base = smem_u32(sm);

    const int tid  = threadIdx.x;
    const int wid  = tid >> 5;
    const int lane = tid & 31;
    const int m0 = blockIdx.y * 128;
    const int n0 = blockIdx.x * 128;
    const int warp_m = (wid & 1) * 64;
    const int warp_n = (wid >> 1) * 32;

    const uint32_t a_off = (uint32_t)((warp_m + (lane & 15)) * ROWB + (lane >> 4) * 16);
    const uint32_t b_off = (uint32_t)((warp_n + (lane & 7) + ((lane >> 4) << 3)) * ROWB
                                      + ((lane >> 3) & 1) * 16);

    float acc[4][4][4];
#pragma unroll
    for (int mf = 0; mf < 4; mf++)
#pragma unroll
        for (int nf = 0; nf < 4; nf++)
#pragma unroll
            for (int r = 0; r < 4; r++) acc[mf][nf][r] = 0.f;

    stage_load(smem_base, 0, m0, n0, tid);
    CP_COMMIT();
    stage_load(smem_base + STAGE_B, 1, m0, n0, tid);
    CP_COMMIT();

    for (int c = 0; c < NCH; c++) {
        if (c + 2 < NCH)
            stage_load(smem_base + (uint32_t)((c + 2) & 3) * STAGE_B, c + 2, m0, n0, tid);
        CP_COMMIT();
        CP_WAIT(2);
        __syncthreads();

        const uint32_t s_cur = smem_base + (uint32_t)(c & 3) * STAGE_B;
#pragma unroll
        for (int ks = 0; ks < 2; ks++) {
            uint32_t ah[4][4], bh[4][2];
#pragma unroll
            for (int mf = 0; mf < 4; mf++)
                LDSM4(ah[mf], s_cur + a_off + (uint32_t)(mf * 16 * ROWB + ks * 32));
#pragma unroll
            for (int ng = 0; ng < 2; ng++) {
                uint32_t r[4];
                LDSM4(r, s_cur + TILE_B + b_off + (uint32_t)(ng * 16 * ROWB + ks * 32));
                bh[2*ng][0]   = r[0]; bh[2*ng][1]   = r[1];
                bh[2*ng+1][0] = r[2]; bh[2*ng+1][1] = r[3];
            }
#pragma unroll
            for (int mf = 0; mf < 4; mf++)
#pragma unroll
                for (int nf = 0; nf < 4; nf++)
                    MMA16816(acc[mf][nf], ah[mf], bh[nf]);
        }
    }

    float2 bias[4];
#pragma unroll
    for (int nf = 0; nf < 4; nf++) {
        const int n = n0 + warp_n + nf * 8 + 2 * (lane & 3);
        bias[nf] = *(const float2*)(bfv + n);
    }
    const int mrow = m0 + warp_m + (lane >> 2);
    const int ncol = n0 + warp_n + 2 * (lane & 3);
#pragma unroll
    for (int mf = 0; mf < 4; mf++) {
#pragma unroll
        for (int nf = 0; nf < 4; nf++) {
            float* p0 = out + (size_t)(mrow + mf * 16) * DOUT + ncol + nf * 8;
            float* p1 = p0 + 8 * DOUT;
            float2 v0 = {acc[mf][nf][0] + bias[nf].x, acc[mf][nf][1] + bias[nf].y};
            float2 v1 = {acc[mf][nf][2] + bias[nf].x, acc[mf][nf][3] + bias[nf].y};
            *(float2*)p0 = v0;
            *(float2*)p1 = v1;
        }
    }
}

// =====================================================================
// launch
// =====================================================================
extern "C" void kernel_launch(void* const* d_in, const int* in_sizes, int n_in,
                              void* d_out, int out_size)
{
    const float* x  = (const float*)d_in[0];
    const float* Wf = (const float*)d_in[1];
    const float* bf = (const float*)d_in[2];
    const float* Wr = (const float*)d_in[3];
    const float* br = (const float*)d_in[4];
    const float* A  = (const float*)d_in[5];
    const float* Bm = (const float*)d_in[6];
    float* out = (float*)d_out;

    const int write_w = (out_size >= MAIN_OUT + W_OUT) ? 1 : 0;

    __half* xh;
    cudaGetSymbolAddress((void**)&xh, g_xh);

    cudaFuncSetAttribute(k_hraw_mma, cudaFuncAttributeMaxDynamicSharedMemorySize, HM_SMEM);
    cudaFuncSetAttribute(k_gemm_mma, cudaFuncAttributeMaxDynamicSharedMemorySize, SMEM_GB);

    k_cvt<<<(M_ * DIN / 4 + 255) / 256, 256>>>(x, xh, M_ * DIN / 4);
    k_prep<<<(NPREP + 255) / 256, 256>>>(Wf, Wr, A, Bm);
    k_hraw_mma<<<M_ / 64, 128, HM_SMEM>>>(br, out + MAIN_OUT, write_w);
    k_gemm_mma<<<dim3(DOUT / 128, M_ / 128), 256, SMEM_GB>>>(bf, out);
}

// round 13
// speedup vs baseline: 7.1866x; 1.0311x over previous
#include <cuda_runtime.h>
#include <cuda_fp16.h>
#include <cstdint>

// ---------------- problem constants ----------------
#define E_      8
#define DIN     2048
#define DOUT    2048
#define RANK    8
#define ER      64
#define M_      8192
#define MAIN_OUT (M_*DOUT)
#define W_OUT    (M_*E_)

// ---------------- scratch (device globals) ----------------
__device__ __align__(16) __half g_xh[(size_t)M_ * DIN];
__device__ __align__(16) __half g_Wh[(size_t)DOUT * DIN];
__device__ __align__(16) __half g_hph[(size_t)M_ * ER];
__device__ __align__(16) __half g_Bsh[(size_t)DOUT * ER];
__device__ __align__(16) __half g_Cat[(size_t)80 * DIN];   // rows 0-7 Wr, 8-71 A, 72-79 zero

// ---------------- PTX helpers (baseline sm_80-class only) ----------------
__device__ __forceinline__ uint32_t smem_u32(const void* p) {
    uint32_t a;
    asm("{ .reg .u64 t; cvta.to.shared.u64 t, %1; cvt.u32.u64 %0, t; }" : "=r"(a) : "l"(p));
    return a;
}
#define CP16(saddr, gptr) \
    asm volatile("cp.async.cg.shared.global [%0], [%1], 16;" :: "r"(saddr), "l"(gptr))
#define CP_COMMIT() asm volatile("cp.async.commit_group;" ::: "memory")
#define CP_WAIT(n)  asm volatile("cp.async.wait_group %0;" :: "n"(n) : "memory")

#define LDSM4(r, a) \
    asm volatile("ldmatrix.sync.aligned.m8n8.x4.shared.b16 {%0,%1,%2,%3}, [%4];" \
        : "=r"((r)[0]), "=r"((r)[1]), "=r"((r)[2]), "=r"((r)[3]) : "r"(a))

#define MMA16816(d, a, b) \
    asm volatile("mma.sync.aligned.m16n8k16.row.col.f32.f16.f16.f32 " \
        "{%0,%1,%2,%3}, {%4,%5,%6,%7}, {%8,%9}, {%0,%1,%2,%3};" \
        : "+f"((d)[0]), "+f"((d)[1]), "+f"((d)[2]), "+f"((d)[3]) \
        : "r"((a)[0]), "r"((a)[1]), "r"((a)[2]), "r"((a)[3]), \
          "r"((b)[0]), "r"((b)[1]))

// =====================================================================
// k_cvt: x fp32 -> fp16
// =====================================================================
__global__ void k_cvt(const float* __restrict__ s, __half* __restrict__ h, int n4)
{
    const int i = blockIdx.x * blockDim.x + threadIdx.x;
    if (i >= n4) return;
    const float4 v = ((const float4*)s)[i];
    ((__half2*)h)[2*i]   = __floats2half2_rn(v.x, v.y);
    ((__half2*)h)[2*i+1] = __floats2half2_rn(v.z, v.w);
}

// =====================================================================
// k_prep (fused): Wf->fp16, BsT transpose->fp16, Cat=[Wr;A;0]->fp16
// =====================================================================
#define NW4   (DOUT*DIN/4)
#define NBS   (DOUT*ER)
#define NCAT2 (80*DIN/2)
#define NPREP (NW4+NBS+NCAT2)

__global__ void k_prep(const float* __restrict__ Wf,
                       const float* __restrict__ Wr,
                       const float* __restrict__ A,
                       const float* __restrict__ Bm)
{
    int i = blockIdx.x * blockDim.x + threadIdx.x;
    if (i < NW4) {
        const float4 v = ((const float4*)Wf)[i];
        ((__half2*)g_Wh)[2*i]   = __floats2half2_rn(v.x, v.y);
        ((__half2*)g_Wh)[2*i+1] = __floats2half2_rn(v.z, v.w);
        return;
    }
    i -= NW4;
    if (i < NBS) {
        const int o = i >> 6;
        const int k = i & 63;
        const float v = Bm[(size_t)(k >> 3) * DOUT * RANK + (size_t)o * RANK + (k & 7)];
        g_Bsh[(size_t)o * ER + k] = __float2half_rn(v);
        return;
    }
    i -= NBS;
    if (i < NCAT2) {
        const int row = i >> 10;
        const int c2  = (i & 1023) * 2;
        float v0 = 0.f, v1 = 0.f;
        if (row < 8)       { v0 = Wr[row * DIN + c2];       v1 = Wr[row * DIN + c2 + 1]; }
        else if (row < 72) { v0 = A[(row - 8) * DIN + c2];  v1 = A[(row - 8) * DIN + c2 + 1]; }
        ((__half2*)g_Cat)[i] = __floats2half2_rn(v0, v1);
    }
}

// =====================================================================
// k_hraw_mma: hraw[8192,72] = xh @ Cat^T, fused softmax epilogue
//   (UNCHANGED from round 9 — measured within helper budget)
// =====================================================================
#define HM_ROWB  144
#define HM_AT    (64*HM_ROWB)
#define HM_BT    (80*HM_ROWB)
#define HM_STAGE (HM_AT+HM_BT)
#define HM_SMEM  (4*HM_STAGE)
#define HM_NCH   32

__device__ __forceinline__ void hm_load(uint32_t s, int c, int tb, int tid)
{
#pragma unroll
    for (int i = 0; i < 4; i++) {
        const int idx = tid + i * 128;
        const int row = idx >> 3, q = idx & 7;
        CP16(s + (uint32_t)(row * HM_ROWB + q * 16),
             g_xh + (size_t)(tb + row) * DIN + c * 64 + q * 8);
    }
#pragma unroll
    for (int i = 0; i < 5; i++) {
        const int idx = tid + i * 128;
        const int row = idx >> 3, q = idx & 7;
        CP16(s + HM_AT + (uint32_t)(row * HM_ROWB + q * 16),
             g_Cat + (size_t)row * DIN + c * 64 + q * 8);
    }
}

__global__ __launch_bounds__(128)
void k_hraw_mma(const float* __restrict__ br, float* __restrict__ wout, int write_w)
{
    extern __shared__ __align__(128) char smh[];
    const uint32_t sb = smem_u32(smh);
    const int tid  = threadIdx.x;
    const int wid  = tid >> 5;
    const int lane = tid & 31;
    const int tb   = blockIdx.x * 64;

    const uint32_t a_off = (uint32_t)((wid * 16 + (lane & 15)) * HM_ROWB + (lane >> 4) * 16);
    const uint32_t b_off = (uint32_t)(((lane & 7) + ((lane >> 4) << 3)) * HM_ROWB
                                      + ((lane >> 3) & 1) * 16);

    float acc[9][4];
#pragma unroll
    for (int nf = 0; nf < 9; nf++)
#pragma unroll
        for (int r = 0; r < 4; r++) acc[nf][r] = 0.f;

    hm_load(sb, 0, tb, tid);
    CP_COMMIT();
    hm_load(sb + HM_STAGE, 1, tb, tid);
    CP_COMMIT();

    for (int c = 0; c < HM_NCH; c++) {
        if (c + 2 < HM_NCH)
            hm_load(sb + (uint32_t)((c + 2) & 3) * HM_STAGE, c + 2, tb, tid);
        CP_COMMIT();
        CP_WAIT(2);
        __syncthreads();

        const uint32_t s_cur = sb + (uint32_t)(c & 3) * HM_STAGE;
#pragma unroll
        for (int ks = 0; ks < 4; ks++) {
            uint32_t ah[4], bh[10][2];
            LDSM4(ah, s_cur + a_off + (uint32_t)(ks * 32));
#pragma unroll
            for (int ng = 0; ng < 5; ng++) {
                uint32_t r[4];
                LDSM4(r, s_cur + HM_AT + b_off + (uint32_t)(ng * 16 * HM_ROWB + ks * 32));
                bh[2*ng][0]   = r[0]; bh[2*ng][1]   = r[1];
                bh[2*ng+1][0] = r[2]; bh[2*ng+1][1] = r[3];
            }
#pragma unroll
            for (int nf = 0; nf < 9; nf++)
                MMA16816(acc[nf], ah, bh[nf]);
        }
    }

    const int q  = lane & 3;
    const int r0 = tb + wid * 16 + (lane >> 2);
    const float b0 = br[2*q], b1 = br[2*q + 1];

    const float a0 = acc[0][0] + b0, a1 = acc[0][1] + b1;
    const float c0 = acc[0][2] + b0, c1 = acc[0][3] + b1;

    float m0 = fmaxf(a0, a1);
    m0 = fmaxf(m0, __shfl_xor_sync(0xffffffffu, m0, 1, 4));
    m0 = fmaxf(m0, __shfl_xor_sync(0xffffffffu, m0, 2, 4));
    float m1 = fmaxf(c0, c1);
    m1 = fmaxf(m1, __shfl_xor_sync(0xffffffffu, m1, 1, 4));
    m1 = fmaxf(m1, __shfl_xor_sync(0xffffffffu, m1, 2, 4));

    const float e00 = __expf(a0 - m0), e01 = __expf(a1 - m0);
    const float e10 = __expf(c0 - m1), e11 = __expf(c1 - m1);
    float s0 = e00 + e01;
    s0 += __shfl_xor_sync(0xffffffffu, s0, 1, 4);
    s0 += __shfl_xor_sync(0xffffffffu, s0, 2, 4);
    float s1 = e10 + e11;
    s1 += __shfl_xor_sync(0xffffffffu, s1, 1, 4);
    s1 += __shfl_xor_sync(0xffffffffu, s1, 2, 4);

    const float p00 = e00 / s0, p01 = e01 / s0;
    const float p10 = e10 / s1, p11 = e11 / s1;

    if (write_w) {
        *(float2*)(wout + (size_t)r0 * E_ + 2*q)       = make_float2(p00, p01);
        *(float2*)(wout + (size_t)(r0 + 8) * E_ + 2*q) = make_float2(p10, p11);
    }

#pragma unroll
    for (int nf = 1; nf < 9; nf++) {
        const int e = nf - 1;
        const int src = (lane & ~3) | (e >> 1);
        const float l0 = __shfl_sync(0xffffffffu, (e & 1) ? p01 : p00, src);
        const float l1 = __shfl_sync(0xffffffffu, (e & 1) ? p11 : p10, src);
        const __half2 h0 = __floats2half2_rn(acc[nf][0] * l0, acc[nf][1] * l0);
        const __half2 h1 = __floats2half2_rn(acc[nf][2] * l1, acc[nf][3] * l1);
        *(__half2*)(g_hph + (size_t)r0 * ER + 8*e + 2*q)       = h0;
        *(__half2*)(g_hph + (size_t)(r0 + 8) * ER + 8*e + 2*q) = h1;
    }
}

// =====================================================================
// Kernel B: mma.sync fp16 GEMM  out = x@Wf^T + bf + hp@BsT^T
//   tile 128x128, BK=64, 33 chunks (32 main + 1 LoRA).
//   3-stage ring, prefetch distance 2, sync-BEFORE-load (slot reuse safe).
//   8 warps (2m x 4n), warp tile 64x32. 110.6KB smem -> 2 CTAs/SM.
// =====================================================================
#define NCH      33
#define ROWB     144            // 128B data + 16B pad (conflict-free ldmatrix)
#define TILE_B   (128*ROWB)     // 18432
#define STAGE_B  (2*TILE_B)     // 36864 (A then B)
#define NSTAGE   3
#define SMEM_GB  (NSTAGE*STAGE_B)   // 110592

__device__ __forceinline__ void stage_load(uint32_t s_stage, int c, int m0, int n0, int tid)
{
    const __half *ga, *gb;
    int stride, koff;
    if (c < 32) {
        ga = g_xh + (size_t)m0 * DIN;
        gb = g_Wh + (size_t)n0 * DIN;
        stride = DIN; koff = c * 64;
    } else {
        ga = g_hph + (size_t)m0 * ER;
        gb = g_Bsh + (size_t)n0 * ER;
        stride = ER; koff = 0;
    }
#pragma unroll
    for (int i = 0; i < 4; i++) {
        const int idx = tid + i * 256;
        const int row = idx >> 3;
        const int q   = idx & 7;
        const uint32_t so = (uint32_t)(row * ROWB + q * 16);
        const size_t go = (size_t)row * stride + koff + q * 8;
        CP16(s_stage + so,          ga + go);
        CP16(s_stage + TILE_B + so, gb + go);
    }
}

__global__ __launch_bounds__(256, 2)
void k_gemm_mma(const float* __restrict__ bfv, float* __restrict__ out)
{
    extern __shared__ __align__(128) char sm[];
    const uint32_t smem_base = smem_u32(sm);

    const int tid  = threadIdx.x;
    const int wid  = tid >> 5;
    const int lane = tid & 31;
    const int m0 = blockIdx.y * 128;
    const int n0 = blockIdx.x * 128;
    const int warp_m = (wid & 1) * 64;
    const int warp_n = (wid >> 1) * 32;

    const uint32_t a_off = (uint32_t)((warp_m + (lane & 15)) * ROWB + (lane >> 4) * 16);
    const uint32_t b_off = (uint32_t)((warp_n + (lane & 7) + ((lane >> 4) << 3)) * ROWB
                                      + ((lane >> 3) & 1) * 16);

    float acc[4][4][4];
#pragma unroll
    for (int mf = 0; mf < 4; mf++)
#pragma unroll
        for (int nf = 0; nf < 4; nf++)
#pragma unroll
            for (int r = 0; r < 4; r++) acc[mf][nf][r] = 0.f;

    // prologue: chunks 0,1 into slots 0,1
    stage_load(smem_base, 0, m0, n0, tid);
    CP_COMMIT();
    stage_load(smem_base + STAGE_B, 1, m0, n0, tid);
    CP_COMMIT();

    int slot = 0;        // slot of chunk c
    for (int c = 0; c < NCH; c++) {
        CP_WAIT(1);          // chunk c complete (c+1 may still be in flight)
        __syncthreads();     // all warps past reads of the slot chunk c+2 will use

        if (c + 2 < NCH) {   // safe: barrier above proves slot (slot+2)%3 drained
            const int ns = (slot + 2) % NSTAGE;
            stage_load(smem_base + (uint32_t)ns * STAGE_B, c + 2, m0, n0, tid);
            CP_COMMIT();
        }

        const uint32_t s_cur = smem_base + (uint32_t)slot * STAGE_B;
#pragma unroll
        for (int ks = 0; ks < 4; ks++) {
            uint32_t ah[4][4], bh[4][2];
#pragma unroll
            for (int mf = 0; mf < 4; mf++)
                LDSM4(ah[mf], s_cur + a_off + (uint32_t)(mf * 16 * ROWB + ks * 32));
#pragma unroll
            for (int ng = 0; ng < 2; ng++) {
                uint32_t r[4];
                LDSM4(r, s_cur + TILE_B + b_off + (uint32_t)(ng * 16 * ROWB + ks * 32));
                bh[2*ng][0]   = r[0]; bh[2*ng][1]   = r[1];
                bh[2*ng+1][0] = r[2]; bh[2*ng+1][1] = r[3];
            }
#pragma unroll
            for (int mf = 0; mf < 4; mf++)
#pragma unroll
                for (int nf = 0; nf < 4; nf++)
                    MMA16816(acc[mf][nf], ah[mf], bh[nf]);
        }
        slot = (slot + 1) % NSTAGE;
    }

    // ---- epilogue: acc -> gmem (+bias)
    float2 bias[4];
#pragma unroll
    for (int nf = 0; nf < 4; nf++) {
        const int n = n0 + warp_n + nf * 8 + 2 * (lane & 3);
        bias[nf] = *(const float2*)(bfv + n);
    }
    const int mrow = m0 + warp_m + (lane >> 2);
    const int ncol = n0 + warp_n + 2 * (lane & 3);
#pragma unroll
    for (int mf = 0; mf < 4; mf++) {
#pragma unroll
        for (int nf = 0; nf < 4; nf++) {
            float* p0 = out + (size_t)(mrow + mf * 16) * DOUT + ncol + nf * 8;
            float* p1 = p0 + 8 * DOUT;
            float2 v0 = {acc[mf][nf][0] + bias[nf].x, acc[mf][nf][1] + bias[nf].y};
            float2 v1 = {acc[mf][nf][2] + bias[nf].x, acc[mf][nf][3] + bias[nf].y};
            *(float2*)p0 = v0;
            *(float2*)p1 = v1;
        }
    }
}

// =====================================================================
// launch
// =====================================================================
extern "C" void kernel_launch(void* const* d_in, const int* in_sizes, int n_in,
                              void* d_out, int out_size)
{
    const float* x  = (const float*)d_in[0];
    const float* Wf = (const float*)d_in[1];
    const float* bf = (const float*)d_in[2];
    const float* Wr = (const float*)d_in[3];
    const float* br = (const float*)d_in[4];
    const float* A  = (const float*)d_in[5];
    const float* Bm = (const float*)d_in[6];
    float* out = (float*)d_out;

    const int write_w = (out_size >= MAIN_OUT + W_OUT) ? 1 : 0;

    __half* xh;
    cudaGetSymbolAddress((void**)&xh, g_xh);

    cudaFuncSetAttribute(k_hraw_mma, cudaFuncAttributeMaxDynamicSharedMemorySize, HM_SMEM);
    cudaFuncSetAttribute(k_gemm_mma, cudaFuncAttributeMaxDynamicSharedMemorySize, SMEM_GB);

    k_cvt<<<(M_ * DIN / 4 + 255) / 256, 256>>>(x, xh, M_ * DIN / 4);
    k_prep<<<(NPREP + 255) / 256, 256>>>(Wf, Wr, A, Bm);
    k_hraw_mma<<<M_ / 64, 128, HM_SMEM>>>(br, out + MAIN_OUT, write_w);
    k_gemm_mma<<<dim3(DOUT / 128, M_ / 128), 256, SMEM_GB>>>(bf, out);
}